// round 1
// baseline (speedup 1.0000x reference)
#include <cuda_runtime.h>

#define NN    16384
#define INF   256
#define OUTF  128

// Scratch for HW = H @ kernel^T  (16384 x 128 fp32 = 8 MB, L2-resident)
__device__ float g_HW[NN * OUTF];

// ---------------------------------------------------------------------------
// Phase 1: HW = H @ W^T.   M=16384, K=256, N=128.
// 256 CTAs, 256 thr. CTA tile 64x128, thread tile 8 rows x 4 cols.
// ---------------------------------------------------------------------------
__global__ __launch_bounds__(256) void hw_gemm(const float* __restrict__ H,
                                               const float* __restrict__ W) {
    __shared__ float hS[64][33];           // H tile (row-padded)
    __shared__ float kS[32][OUTF + 4];     // W tile: kS[kk][o], stride 132
                                           // (132*4B % 16B == 0 -> aligned f4,
                                           //  quarter-warp f4 reads conflict-free)
    const int tid  = threadIdx.x;
    const int tc   = tid & 31;             // col group: cols [tc*4, tc*4+3]
    const int trg  = tid >> 5;             // row group: rows [trg*8, trg*8+7]
    const int row0 = blockIdx.x * 64;

    float acc[8][4];
#pragma unroll
    for (int r = 0; r < 8; r++)
#pragma unroll
        for (int c = 0; c < 4; c++) acc[r][c] = 0.f;

    for (int k0 = 0; k0 < INF; k0 += 32) {
        // H tile 64x32 (coalesced 128B rows; smem writes conflict-free)
#pragma unroll
        for (int p = 0; p < 8; p++) {
            int idx = p * 256 + tid;
            int r = idx >> 5, kk = idx & 31;
            hS[r][kk] = H[(size_t)(row0 + r) * INF + k0 + kk];
        }
        // W tile 32x128 -> kS[kk][o]. Global coalesced over kk.
#pragma unroll
        for (int p = 0; p < 16; p++) {
            int idx = p * 256 + tid;
            int o = idx >> 5, kk = idx & 31;
            kS[kk][o] = W[(size_t)o * INF + k0 + kk];
        }
        __syncthreads();
#pragma unroll
        for (int kk = 0; kk < 32; kk++) {
            float4 b = *(const float4*)&kS[kk][tc * 4];
#pragma unroll
            for (int r = 0; r < 8; r++) {
                float a = hS[trg * 8 + r][kk];   // warp-uniform broadcast
                acc[r][0] += a * b.x;
                acc[r][1] += a * b.y;
                acc[r][2] += a * b.z;
                acc[r][3] += a * b.w;
            }
        }
        __syncthreads();
    }
#pragma unroll
    for (int r = 0; r < 8; r++) {
        float4 v = make_float4(acc[r][0], acc[r][1], acc[r][2], acc[r][3]);
        *(float4*)&g_HW[(size_t)(row0 + trg * 8 + r) * OUTF + tc * 4] = v;
    }
}

// ---------------------------------------------------------------------------
// Phase 2: per-row nonzero scan of A + gather-sum of HW rows.
// One CTA per row i. 256 threads stream A[i,:] (64 KB) as streaming float4,
// collect nonzero column indices in smem, then accumulate HW rows (L2 hits).
// out[i][c] = (sum_{j in nnz(i)} HW[j][c]) / (deg_i + 1)
// ---------------------------------------------------------------------------
#define MAXNNZ 2048

__global__ __launch_bounds__(256) void aggregate(const float* __restrict__ A,
                                                 float* __restrict__ out) {
    __shared__ int   s_idx[MAXNNZ];
    __shared__ int   s_cnt;
    __shared__ float s_red[OUTF];

    const int tid = threadIdx.x;
    const size_t row = blockIdx.x;

    if (tid == 0) s_cnt = 0;
    __syncthreads();

    const float4* Arow = (const float4*)(A + row * NN);
#pragma unroll
    for (int it = 0; it < NN / (256 * 4); it++) {   // 16 iters, MLP-friendly
        int q = it * 256 + tid;                     // float4 index (coalesced)
        float4 v = __ldcs(&Arow[q]);                // streaming: keep HW in L2
        int base = q * 4;
        if (v.x != 0.f) { int p = atomicAdd(&s_cnt, 1); if (p < MAXNNZ) s_idx[p] = base;     }
        if (v.y != 0.f) { int p = atomicAdd(&s_cnt, 1); if (p < MAXNNZ) s_idx[p] = base + 1; }
        if (v.z != 0.f) { int p = atomicAdd(&s_cnt, 1); if (p < MAXNNZ) s_idx[p] = base + 2; }
        if (v.w != 0.f) { int p = atomicAdd(&s_cnt, 1); if (p < MAXNNZ) s_idx[p] = base + 3; }
    }
    __syncthreads();

    const int cnt = s_cnt;                          // degree
    const int lim = cnt < MAXNNZ ? cnt : MAXNNZ;
    const int c = tid & 127;                        // output column
    const int h = tid >> 7;                         // half: 0/1 alternate nnz

    float acc = 0.f;
    for (int k = h; k < lim; k += 2)
        acc += g_HW[(size_t)s_idx[k] * OUTF + c];   // coalesced 512B, L2 hit

    if (h == 1) s_red[c] = acc;
    __syncthreads();
    if (h == 0) {
        float total = acc + s_red[c];
        out[row * OUTF + c] = total / (float)(cnt + 1);
    }
}

extern "C" void kernel_launch(void* const* d_in, const int* in_sizes, int n_in,
                              void* d_out, int out_size) {
    const float* A = (const float*)d_in[0];   // [16384, 16384]
    const float* H = (const float*)d_in[1];   // [16384, 256]
    const float* W = (const float*)d_in[2];   // [128, 256]
    float* out = (float*)d_out;               // [16384, 128]

    float* hw;
    cudaGetSymbolAddress((void**)&hw, g_HW);  // host-side, capture-safe
    (void)hw; (void)in_sizes; (void)n_in; (void)out_size;

    hw_gemm<<<NN / 64, 256>>>(H, W);
    aggregate<<<NN, 256>>>(A, out);
}